// round 11
// baseline (speedup 1.0000x reference)
#include <cuda_runtime.h>
#include <cuda_bf16.h>
#include <cstdint>
#include <float.h>
#include <math.h>

#define BATCH 4
#define HW    4096
#define CDIM  256
#define NSTRIP 32
#define EPSQ  1e-9f
#define TLC   0.6f
#define LC    2.0f
#define MARGIN 0.75f
#define ACH   16384               // one 128x64 bf16 chunk, XOR-swizzled, no pad
#define DYNSMEM (6 * ACH)         // A: 4 chunks (64KB) + B: 2 chunks (32KB)
#define NCTA  74                  // per batch; 296 total = 2/SM exactly

// static device scratch
__device__ __nv_bfloat16 g_xhi[BATCH * HW * CDIM];
__device__ float    g_norms[BATCH * HW];
__device__ uint32_t g_pc[(size_t)BATCH * HW * NSTRIP * 4];  // packed (val25|idx7)
__device__ int      g_flagcnt;
__device__ int      g_flaglist[BATCH * HW];

// ---------------------------------------------------------------------------
__device__ __forceinline__ uint32_t smem_u32(const void* p) {
    uint32_t a;
    asm("{ .reg .u64 t; cvta.to.shared.u64 t, %1; cvt.u32.u64 %0, t; }"
        : "=r"(a) : "l"(p));
    return a;
}
__device__ __forceinline__ void cp16(uint32_t dst, const void* src) {
    asm volatile("cp.async.cg.shared.global [%0], [%1], 16;" :: "r"(dst), "l"(src));
}
__device__ __forceinline__ void cp_commit() {
    asm volatile("cp.async.commit_group;" ::: "memory");
}
template <int N> __device__ __forceinline__ void cp_wait() {
    asm volatile("cp.async.wait_group %0;" :: "n"(N) : "memory");
}
__device__ __forceinline__ void ldsm_x4(uint32_t (&r)[4], uint32_t addr) {
    asm volatile("ldmatrix.sync.aligned.m8n8.x4.shared.b16 {%0,%1,%2,%3}, [%4];"
                 : "=r"(r[0]), "=r"(r[1]), "=r"(r[2]), "=r"(r[3]) : "r"(addr));
}
__device__ __forceinline__ uint32_t redux_min_u32(uint32_t v) {
    uint32_t r;
    asm volatile("redux.sync.min.u32 %0, %1, 0xffffffff;" : "=r"(r) : "r"(v));
    return r;
}
#define MMA16816(d, a, b0_, b1_)                                                 \
    asm volatile("mma.sync.aligned.m16n8k16.row.col.f32.bf16.bf16.f32 "          \
                 "{%0,%1,%2,%3}, {%4,%5,%6,%7}, {%8,%9}, {%0,%1,%2,%3};"         \
                 : "+f"((d)[0]), "+f"((d)[1]), "+f"((d)[2]), "+f"((d)[3])        \
                 : "r"((a)[0]), "r"((a)[1]), "r"((a)[2]), "r"((a)[3]),           \
                   "r"(b0_), "r"(b1_))

// swizzled D-tile word index (r in 0..63 here; pattern repeats mod 32)
__device__ __forceinline__ int dsw(int r, int c) {
    return r * 128 + ((((c >> 2) ^ (r & 31)) << 2) | (c & 3));
}
__device__ __forceinline__ bool ltp(float av, int ai, float bv, int bi) {
    return (av < bv) || (av == bv && ai < bi);
}
__device__ __forceinline__ void ceu(uint32_t& a, uint32_t& b) {
    uint32_t mn = min(a, b);
    b = max(a, b);
    a = mn;
}
__device__ __forceinline__ void sort4u(uint32_t (&k)[4]) {
    ceu(k[0], k[1]); ceu(k[2], k[3]);
    ceu(k[0], k[2]); ceu(k[1], k[3]);
    ceu(k[1], k[2]);
}
__device__ __forceinline__ float predict(float m1, float m2) {
    float d1 = sqrtf(fmaxf(m1, 0.f) + EPSQ);
    float d2 = sqrtf(fmaxf(m2, 0.f) + EPSQ);
    float e  = expf(d1);
    return (d1 / d2 < TLC) ? 2.f / (1.f + e) : 2.f / (1.f + LC * e);
}

// ---------------------------------------------------------------------------
// Kernel 1: fused bf16 convert + fp32 row norms (one warp per row)
// ---------------------------------------------------------------------------
__global__ void convert_norms_kernel(const float* __restrict__ x) {
    if (blockIdx.x == 0 && threadIdx.x == 0) g_flagcnt = 0;
    int gw   = (blockIdx.x * blockDim.x + threadIdx.x) >> 5;
    int lane = threadIdx.x & 31;
    if (gw >= BATCH * HW) return;
    const float* xr = x + (size_t)gw * CDIM + lane * 8;
    float4 v0 = *(const float4*)xr;
    float4 v1 = *(const float4*)(xr + 4);
    float s = v0.x*v0.x + v0.y*v0.y + v0.z*v0.z + v0.w*v0.w
            + v1.x*v1.x + v1.y*v1.y + v1.z*v1.z + v1.w*v1.w;
    __nv_bfloat162 p0(__float2bfloat16(v0.x), __float2bfloat16(v0.y));
    __nv_bfloat162 p1(__float2bfloat16(v0.z), __float2bfloat16(v0.w));
    __nv_bfloat162 p2(__float2bfloat16(v1.x), __float2bfloat16(v1.y));
    __nv_bfloat162 p3(__float2bfloat16(v1.z), __float2bfloat16(v1.w));
    uint4 u;
    u.x = *(uint32_t*)&p0; u.y = *(uint32_t*)&p1;
    u.z = *(uint32_t*)&p2; u.w = *(uint32_t*)&p3;
    ((uint4*)g_xhi)[(size_t)gw * 32 + lane] = u;
    #pragma unroll
    for (int o = 16; o; o >>= 1) s += __shfl_xor_sync(0xffffffffu, s, o);
    if (lane == 0) g_norms[gw] = s;
}

// ---------------------------------------------------------------------------
// Kernel 2: persistent multi-tile pair kernel. A strip resident across an
// i-run; B streamed (skipped on diagonal tiles); two-half extraction.
// ---------------------------------------------------------------------------
__global__ __launch_bounds__(512, 2)
void fcm_pair_kernel() {
    extern __shared__ __align__(16) char smem[];
    __shared__ uint32_t colbuf[512];       // half0 col sorted-4 per column
    const uint32_t Abase = smem_u32(smem);
    const uint32_t Bbase = Abase + 4 * ACH;

    const int tid  = threadIdx.x;
    const int lane = tid & 31;
    const int w    = tid >> 5;
    const int mw   = w >> 2;
    const int nw   = w & 3;
    const int b    = blockIdx.y;

    // pair range: first 10 CTAs take 8 pairs, rest 7 (total 528)
    const int extra  = min((int)blockIdx.x, 10);
    int p = blockIdx.x * 7 + extra;
    const int npairs = 7 + (blockIdx.x < 10 ? 1 : 0);

    int i = (int)((65.0f - sqrtf(4225.0f - 8.0f * (float)p)) * 0.5f);
    while ((i + 1) * (65 - (i + 1)) / 2 <= p) ++i;
    while (i * (65 - i) / 2 > p) --i;
    int j = i + (p - i * (65 - i) / 2);

    const __nv_bfloat16* xb = g_xhi + (size_t)b * HW * CDIM;
    const int lrow = ((lane >> 3) & 1) * 8 + (lane & 7);
    const int hi16 = lane >> 4;

    auto stageA = [&](int row0) {
        #pragma unroll
        for (int kc = 0; kc < 4; ++kc)
            #pragma unroll
            for (int o = 0; o < 2; ++o) {
                int lin = tid + o * 512;
                int r = lin >> 3, g = lin & 7;
                cp16(Abase + (uint32_t)(kc * ACH + r * 128 + ((g ^ (r & 7)) << 4)),
                     xb + (size_t)(row0 + r) * CDIM + kc * 64 + g * 8);
            }
        cp_commit();
    };
    auto stageB = [&](int col0, int kc) {
        uint32_t dst = Bbase + (uint32_t)((kc & 1) * ACH);
        #pragma unroll
        for (int o = 0; o < 2; ++o) {
            int lin = tid + o * 512;
            int r = lin >> 3, g = lin & 7;
            cp16(dst + (uint32_t)(r * 128 + ((g ^ (r & 7)) << 4)),
                 xb + (size_t)(col0 + r) * CDIM + kc * 64 + g * 8);
        }
        cp_commit();
    };

    int cur_i = -1;
    for (int t = 0; t < npairs; ++t) {
        const int row0 = i * 128, col0 = j * 128;
        const bool diag = (i == j);

        if (i != cur_i) { stageA(row0); cur_i = i; }
        if (!diag) stageB(col0, 0);

        float acc[2][4][4];
        #pragma unroll
        for (int mf = 0; mf < 2; ++mf)
            #pragma unroll
            for (int nf = 0; nf < 4; ++nf)
                #pragma unroll
                for (int e = 0; e < 4; ++e) acc[mf][nf][e] = 0.f;

        for (int kc = 0; kc < 4; ++kc) {
            cp_wait<0>();
            __syncthreads();
            if (kc < 3 && !diag) stageB(col0, kc + 1);
            const uint32_t abase = Abase + (uint32_t)(kc * ACH);
            const uint32_t bbase = diag ? abase : (Bbase + (uint32_t)((kc & 1) * ACH));
            const int ra = mw * 32 + lrow;
            const int rb = nw * 32 + lrow;
            const uint32_t am = (uint32_t)(lrow & 7);
            #pragma unroll
            for (int ks = 0; ks < 4; ++ks) {
                const uint32_t goff = (((uint32_t)(ks * 2 + hi16) ^ am) << 4);
                uint32_t ah[2][4], bh[2][4];
                ldsm_x4(ah[0], abase + (uint32_t)(ra * 128) + goff);
                ldsm_x4(ah[1], abase + (uint32_t)((ra + 16) * 128) + goff);
                ldsm_x4(bh[0], bbase + (uint32_t)(rb * 128) + goff);
                ldsm_x4(bh[1], bbase + (uint32_t)((rb + 16) * 128) + goff);
                #pragma unroll
                for (int mf = 0; mf < 2; ++mf)
                    #pragma unroll
                    for (int nf = 0; nf < 4; ++nf)
                        MMA16816(acc[mf][nf], ah[mf],
                                 bh[nf >> 1][nf & 1], bh[nf >> 1][(nf & 1) + 2]);
            }
        }
        __syncthreads();               // all ldsm done; B region free for D

        // ---- two-half extraction: half h = rows {mw*32 + h*16 + 0..15} ----
        float* Dt = (float*)(smem + 4 * ACH);
        const float* nbp = g_norms + b * HW + col0 + nw * 32 + (lane & 3) * 2;
        #pragma unroll
        for (int h = 0; h < 2; ++h) {
            {   // write D half from acc[h]; packed row r'' = mw*16 + s
                const int r0  = mw * 16 + (lane >> 2);
                const int rl0 = mw * 32 + h * 16 + (lane >> 2);
                const float na0 = g_norms[b * HW + row0 + rl0];
                const float na1 = g_norms[b * HW + row0 + rl0 + 8];
                #pragma unroll
                for (int nf = 0; nf < 4; ++nf) {
                    float2 nb = *(const float2*)(nbp + nf * 8);
                    int cl = nw * 32 + nf * 8 + (lane & 3) * 2;
                    float2 d0 = { na0 + nb.x - 2.f * acc[h][nf][0],
                                  na0 + nb.y - 2.f * acc[h][nf][1] };
                    float2 d1 = { na1 + nb.x - 2.f * acc[h][nf][2],
                                  na1 + nb.y - 2.f * acc[h][nf][3] };
                    *(float2*)&Dt[dsw(r0, cl)]     = d0;
                    *(float2*)&Dt[dsw(r0 + 8, cl)] = d1;
                }
            }
            __syncthreads();

            // row tasks: 64 packed rows, warp w -> rr = w*4 + {0..3}, 2-ILP
            #pragma unroll
            for (int it = 0; it < 2; ++it) {
                uint32_t k[2][4];
                int rl_[2];
                #pragma unroll
                for (int u = 0; u < 2; ++u) {
                    const int rr = w * 4 + it * 2 + u;
                    const int rl = ((rr >> 4) << 5) + (h << 4) + (rr & 15);
                    rl_[u] = rl;
                    const float4 dv =
                        *(const float4*)&Dt[rr * 128 + ((lane ^ (rr & 31)) << 2)];
                    k[u][0] = (__float_as_uint(dv.x) & 0xFFFFFF80u) | (lane * 4 + 0);
                    k[u][1] = (__float_as_uint(dv.y) & 0xFFFFFF80u) | (lane * 4 + 1);
                    k[u][2] = (__float_as_uint(dv.z) & 0xFFFFFF80u) | (lane * 4 + 2);
                    k[u][3] = (__float_as_uint(dv.w) & 0xFFFFFF80u) | (lane * 4 + 3);
                    if (diag && (rl >> 2) == lane) k[u][rl & 3] = 0xFFFFFFFFu;
                    sort4u(k[u]);
                }
                uint32_t myk[2];
                #pragma unroll
                for (int pp = 0; pp < 4; ++pp) {
                    uint32_t g0 = redux_min_u32(k[0][0]);
                    uint32_t g1 = redux_min_u32(k[1][0]);
                    if (lane == pp) { myk[0] = g0; myk[1] = g1; }
                    if (k[0][0] == g0) {
                        k[0][0] = k[0][1]; k[0][1] = k[0][2];
                        k[0][2] = k[0][3]; k[0][3] = 0xFFFFFFFFu;
                    }
                    if (k[1][0] == g1) {
                        k[1][0] = k[1][1]; k[1][1] = k[1][2];
                        k[1][2] = k[1][3]; k[1][3] = 0xFFFFFFFFu;
                    }
                }
                if (lane < 4) {
                    #pragma unroll
                    for (int u = 0; u < 2; ++u)
                        g_pc[(((size_t)(b * HW + row0 + rl_[u])) * NSTRIP + j) * 4
                             + lane] = myk[u];
                }
            }

            // col tasks: 128 cols, warp w -> c = w*8 + {0..7}, 2-ILP
            if (!diag) {
                #pragma unroll
                for (int it = 0; it < 4; ++it) {
                    uint32_t k[2][2];
                    #pragma unroll
                    for (int u = 0; u < 2; ++u) {
                        const int c = w * 8 + it * 2 + u;
                        const int cb = c >> 2, cq = c & 3;
                        #pragma unroll
                        for (int q = 0; q < 2; ++q) {
                            const int rr = lane + 32 * q;
                            const int rl = ((rr >> 4) << 5) + (h << 4) + (rr & 15);
                            k[u][q] = (__float_as_uint(
                                Dt[rr * 128 + (((cb ^ (rr & 31)) << 2) | cq)])
                                & 0xFFFFFF80u) | (uint32_t)rl;
                        }
                        ceu(k[u][0], k[u][1]);
                    }
                    uint32_t myk[2];
                    #pragma unroll
                    for (int pp = 0; pp < 4; ++pp) {
                        uint32_t g0 = redux_min_u32(k[0][0]);
                        uint32_t g1 = redux_min_u32(k[1][0]);
                        if (lane == pp) { myk[0] = g0; myk[1] = g1; }
                        if (k[0][0] == g0) { k[0][0] = k[0][1]; k[0][1] = 0xFFFFFFFFu; }
                        if (k[1][0] == g1) { k[1][0] = k[1][1]; k[1][1] = 0xFFFFFFFFu; }
                    }
                    if (h == 0) {
                        if (lane < 4) {
                            colbuf[(w * 8 + it * 2 + 0) * 4 + lane] = myk[0];
                            colbuf[(w * 8 + it * 2 + 1) * 4 + lane] = myk[1];
                        }
                    } else {
                        uint32_t m[2][2];
                        if (lane < 4) {
                            m[0][0] = myk[0];
                            m[0][1] = colbuf[(w * 8 + it * 2 + 0) * 4 + lane];
                            m[1][0] = myk[1];
                            m[1][1] = colbuf[(w * 8 + it * 2 + 1) * 4 + lane];
                            ceu(m[0][0], m[0][1]); ceu(m[1][0], m[1][1]);
                        } else {
                            m[0][0] = m[0][1] = 0xFFFFFFFFu;
                            m[1][0] = m[1][1] = 0xFFFFFFFFu;
                        }
                        uint32_t fk[2];
                        #pragma unroll
                        for (int pp = 0; pp < 4; ++pp) {
                            uint32_t g0 = redux_min_u32(m[0][0]);
                            uint32_t g1 = redux_min_u32(m[1][0]);
                            if (lane == pp) { fk[0] = g0; fk[1] = g1; }
                            if (m[0][0] == g0) { m[0][0] = m[0][1]; m[0][1] = 0xFFFFFFFFu; }
                            if (m[1][0] == g1) { m[1][0] = m[1][1]; m[1][1] = 0xFFFFFFFFu; }
                        }
                        if (lane < 4) {
                            const int c0g = col0 + w * 8 + it * 2;
                            g_pc[(((size_t)(b * HW + c0g)) * NSTRIP + i) * 4 + lane] = fk[0];
                            g_pc[(((size_t)(b * HW + c0g + 1)) * NSTRIP + i) * 4 + lane] = fk[1];
                        }
                    }
                }
            }
            __syncthreads();           // D reuse (next half / next tile's B0)
        }

        if (++j == 32) { ++i; j = i; }
    }
}

// ---------------------------------------------------------------------------
// Kernel 3: warp-per-row merge (packed-key pop-min over 32 slot lists) +
// exact fp32 refinement of 8 candidates + margin flagging.
// ---------------------------------------------------------------------------
__global__ void merge_refine_kernel(const float* __restrict__ x,
                                    float* __restrict__ out, int out_size) {
    int gw   = (blockIdx.x * blockDim.x + threadIdx.x) >> 5;
    int lane = threadIdx.x & 31;
    if (gw >= BATCH * HW) return;
    const int b = gw >> 12, rl = gw & 4095;

    const uint4 kk = *(const uint4*)(g_pc + ((size_t)gw * NSTRIP + lane) * 4);
    const uint32_t b1 = redux_min_u32(kk.w);

    const uint32_t base = (uint32_t)lane * 128u;
    uint32_t mk[4];
    mk[0] = (kk.x & 0xFFFFF000u) | (base + (kk.x & 0x7Fu));
    mk[1] = (kk.y & 0xFFFFF000u) | (base + (kk.y & 0x7Fu));
    mk[2] = (kk.z & 0xFFFFF000u) | (base + (kk.z & 0x7Fu));
    mk[3] = (kk.w & 0xFFFFF000u) | (base + (kk.w & 0x7Fu));
    sort4u(mk);

    uint32_t gks[8];
    #pragma unroll
    for (int pp = 0; pp < 8; ++pp) {
        uint32_t gv = redux_min_u32(mk[0]);
        gks[pp] = gv;
        if (mk[0] == gv) {
            mk[0] = mk[1]; mk[1] = mk[2]; mk[2] = mk[3]; mk[3] = 0xFFFFFFFFu;
        }
    }

    const float* xb = x + (size_t)b * HW * CDIM;
    const float* xr = xb + (size_t)rl * CDIM + lane * 8;
    float4 a0 = *(const float4*)xr;
    float4 a1 = *(const float4*)(xr + 4);
    const float nr = g_norms[b * HW + rl];

    float m1 = FLT_MAX, m2 = FLT_MAX; int j1 = 0, j2 = 0;
    #pragma unroll
    for (int k = 0; k < 8; ++k) {
        const int c = (int)(gks[k] & 0xFFFu);
        const float* xc = xb + (size_t)c * CDIM + lane * 8;
        float4 c0 = *(const float4*)xc;
        float4 c1 = *(const float4*)(xc + 4);
        float s = a0.x*c0.x + a0.y*c0.y + a0.z*c0.z + a0.w*c0.w
                + a1.x*c1.x + a1.y*c1.y + a1.z*c1.z + a1.w*c1.w;
        #pragma unroll
        for (int off = 16; off; off >>= 1) s += __shfl_xor_sync(0xffffffffu, s, off);
        float D = nr + g_norms[b * HW + c] - 2.f * s;
        if (ltp(D, c, m1, j1)) { m2 = m1; j2 = j1; m1 = D; j1 = c; }
        else if (ltp(D, c, m2, j2)) { m2 = D; j2 = c; }
    }

    if (lane == 0) {
        out[(size_t)b * HW + rl] = predict(m1, m2);
        if (out_size >= 2 * BATCH * HW)
            out[(size_t)BATCH * HW + (size_t)b * HW + rl] = (float)j1;
        float bound = fminf(__uint_as_float(b1 & 0xFFFFFF80u),
                            __uint_as_float(gks[7] & 0xFFFFF000u));
        if (m2 > bound - MARGIN) {
            int fi = atomicAdd(&g_flagcnt, 1);
            g_flaglist[fi] = gw;
        }
    }
}

// ---------------------------------------------------------------------------
// Kernel 4: exact full-row rescan for flagged rows (expected ~0 rows).
// ---------------------------------------------------------------------------
__global__ void fallback_kernel(const float* __restrict__ x,
                                float* __restrict__ out, int out_size) {
    __shared__ float sv1[256], sv2[256];
    __shared__ int   si1[256];
    const int n = g_flagcnt;
    for (int fi = blockIdx.x; fi < n; fi += gridDim.x) {
        const int rowg = g_flaglist[fi];
        const int b = rowg >> 12, r = rowg & 4095;
        const float* xb = x + (size_t)b * HW * CDIM;
        const float* xr = xb + (size_t)r * CDIM;
        const float  nr = g_norms[rowg];
        float v1 = FLT_MAX, v2 = FLT_MAX; int i1 = 0x7fffffff;
        for (int c = threadIdx.x; c < HW; c += 256) {
            if (c == r) continue;
            const float4* xc = (const float4*)(xb + (size_t)c * CDIM);
            float s = 0.f;
            #pragma unroll
            for (int d = 0; d < 64; ++d) {
                float4 va = ((const float4*)xr)[d];
                float4 vb = xc[d];
                s += va.x*vb.x + va.y*vb.y + va.z*vb.z + va.w*vb.w;
            }
            float D = nr + g_norms[b * HW + c] - 2.f * s;
            if (ltp(D, c, v1, i1)) { v2 = v1; v1 = D; i1 = c; }
            else if (D < v2) { v2 = D; }
        }
        sv1[threadIdx.x] = v1; sv2[threadIdx.x] = v2; si1[threadIdx.x] = i1;
        __syncthreads();
        for (int off = 128; off; off >>= 1) {
            if (threadIdx.x < off) {
                float b1 = sv1[threadIdx.x + off], b2 = sv2[threadIdx.x + off];
                int   bi = si1[threadIdx.x + off];
                float a1v = sv1[threadIdx.x]; int a1i = si1[threadIdx.x];
                if (ltp(b1, bi, a1v, a1i)) {
                    sv2[threadIdx.x] = fminf(a1v, b2);
                    sv1[threadIdx.x] = b1; si1[threadIdx.x] = bi;
                } else {
                    sv2[threadIdx.x] = fminf(sv2[threadIdx.x], b1);
                }
            }
            __syncthreads();
        }
        if (threadIdx.x == 0) {
            out[(size_t)b * HW + r] = predict(sv1[0], sv2[0]);
            if (out_size >= 2 * BATCH * HW)
                out[(size_t)BATCH * HW + (size_t)b * HW + r] = (float)si1[0];
        }
        __syncthreads();
    }
}

// ---------------------------------------------------------------------------
extern "C" void kernel_launch(void* const* d_in, const int* in_sizes, int n_in,
                              void* d_out, int out_size) {
    const float* x   = (const float*)d_in[0];
    float*       out = (float*)d_out;

    convert_norms_kernel<<<BATCH * HW / 8, 256>>>(x);

    cudaFuncSetAttribute(fcm_pair_kernel,
                         cudaFuncAttributeMaxDynamicSharedMemorySize, DYNSMEM);
    dim3 grid(NCTA, BATCH);
    fcm_pair_kernel<<<grid, 512, DYNSMEM>>>();

    merge_refine_kernel<<<BATCH * HW / 8, 256>>>(x, out, out_size);
    fallback_kernel<<<256, 256>>>(x, out, out_size);
}